// round 1
// baseline (speedup 1.0000x reference)
#include <cuda_runtime.h>
#include <cstdint>

#define HIDDEN    450
#define ATOM_FDIM 35
#define BOND_FDIM 5
#define MAX_NB    15

#define MAX_BONDS 40000
#define MAX_ATOMS 20000

// ---------------- scratch (static device globals; no runtime allocation) ----
__device__ float g_binput[(size_t)MAX_BONDS * HIDDEN];  // pre-relu bond input; reused as atom_hiddens at the end
__device__ float g_gmsg  [(size_t)MAX_BONDS * HIDDEN];  // graph_message
__device__ float g_nei   [(size_t)MAX_BONDS * HIDDEN];  // gathered neighbor sums (bonds or atoms)

// ---------------- GEMM ------------------------------------------------------
// C[m][n] = epilogue( sum_k A[m][k] * W[n][k] )
// MODE 0: C = t, C2 = relu(t)                (init layer, A = fbonds, K=40)
// MODE 1: C = relu(t + biasM[m][n])          (message layers, A = nei, K=450)
// MODE 2: C = relu(t + biasV[n]), A = concat(A1[:,0:K1], A2[:,:])  (output layer, K=485)
#define BM 64
#define BN 64
#define BK 16
#define SPAD 68   // 68*4 = 272 bytes, 16B-aligned rows for float4 LDS

template <int MODE>
__global__ __launch_bounds__(256)
void gemm_kernel(const float* __restrict__ A, const float* __restrict__ A2, int K1,
                 const float* __restrict__ W, int ldw,
                 const float* __restrict__ biasM, const float* __restrict__ biasV,
                 float* __restrict__ C, float* __restrict__ C2,
                 int M, int N, int K)
{
    __shared__ float As[BK][SPAD];
    __shared__ float Ws[BK][SPAD];

    const int tid = threadIdx.x;        // 256 threads
    const int tx  = tid & 15;           // 0..15 -> output cols (x4)
    const int ty  = tid >> 4;           // 0..15 -> output rows (x4)
    const int row0 = blockIdx.y * BM;
    const int col0 = blockIdx.x * BN;

    float acc[4][4];
#pragma unroll
    for (int i = 0; i < 4; i++)
#pragma unroll
        for (int j = 0; j < 4; j++) acc[i][j] = 0.f;

    for (int k0 = 0; k0 < K; k0 += BK) {
        // --- load A tile [BM x BK], store transposed As[k][m]
#pragma unroll
        for (int i = tid; i < BM * BK; i += 256) {
            int r = i >> 4;            // 0..63
            int c = i & 15;            // 0..15
            int gr = row0 + r;
            int gk = k0 + c;
            float v = 0.f;
            if (gr < M && gk < K) {
                if (MODE == 2) {
                    v = (gk < K1) ? A[(size_t)gr * K1 + gk]
                                  : A2[(size_t)gr * HIDDEN + (gk - K1)];
                } else {
                    v = A[(size_t)gr * K + gk];
                }
            }
            As[c][r] = v;
        }
        // --- load W tile [BN x BK], store transposed Ws[k][n]
#pragma unroll
        for (int i = tid; i < BN * BK; i += 256) {
            int r = i >> 4;
            int c = i & 15;
            int gn = col0 + r;
            int gk = k0 + c;
            float v = 0.f;
            if (gn < N && gk < K) v = W[(size_t)gn * ldw + gk];
            Ws[c][r] = v;
        }
        __syncthreads();

#pragma unroll
        for (int kk = 0; kk < BK; kk++) {
            float4 a = *(const float4*)&As[kk][ty * 4];
            float4 w = *(const float4*)&Ws[kk][tx * 4];
            acc[0][0] += a.x * w.x; acc[0][1] += a.x * w.y; acc[0][2] += a.x * w.z; acc[0][3] += a.x * w.w;
            acc[1][0] += a.y * w.x; acc[1][1] += a.y * w.y; acc[1][2] += a.y * w.z; acc[1][3] += a.y * w.w;
            acc[2][0] += a.z * w.x; acc[2][1] += a.z * w.y; acc[2][2] += a.z * w.z; acc[2][3] += a.z * w.w;
            acc[3][0] += a.w * w.x; acc[3][1] += a.w * w.y; acc[3][2] += a.w * w.z; acc[3][3] += a.w * w.w;
        }
        __syncthreads();
    }

    // --- epilogue
#pragma unroll
    for (int i = 0; i < 4; i++) {
        int gr = row0 + ty * 4 + i;
        if (gr >= M) continue;
#pragma unroll
        for (int j = 0; j < 4; j++) {
            int gc = col0 + tx * 4 + j;
            if (gc >= N) continue;
            float t = acc[i][j];
            size_t o = (size_t)gr * N + gc;
            if (MODE == 0) {
                C[o]  = t;
                C2[o] = t > 0.f ? t : 0.f;
            } else if (MODE == 1) {
                t += biasM[o];
                C[o] = t > 0.f ? t : 0.f;
            } else {
                t += biasV[gc];
                C[o] = t > 0.f ? t : 0.f;
            }
        }
    }
}

// ---------------- neighbor gather-sum ---------------------------------------
// out[b][:] = sum_{nb<MAX_NB} message[graph[b][nb]][:]
// message = concat(tree_message [n_mess rows], gmsg [n rows])
__global__ __launch_bounds__(256)
void gather_sum_kernel(const int* __restrict__ graph,
                       const float* __restrict__ tree, int n_mess,
                       const float* __restrict__ gmsg,
                       float* __restrict__ out)
{
    const int b = blockIdx.x;
    __shared__ const float* rows[MAX_NB];
    if (threadIdx.x < MAX_NB) {
        int id = graph[(size_t)b * MAX_NB + threadIdx.x];
        rows[threadIdx.x] = (id < n_mess) ? (tree + (size_t)id * HIDDEN)
                                          : (gmsg + (size_t)(id - n_mess) * HIDDEN);
    }
    __syncthreads();

    const int t = threadIdx.x;
    if (t < HIDDEN / 2) {              // 225 float2 per row
        float2 acc = make_float2(0.f, 0.f);
#pragma unroll
        for (int nb = 0; nb < MAX_NB; nb++) {
            float2 v = ((const float2*)rows[nb])[t];
            acc.x += v.x;
            acc.y += v.y;
        }
        ((float2*)(out + (size_t)b * HIDDEN))[t] = acc;
    }
}

// ---------------- per-molecule mean -----------------------------------------
// mol_ids is sorted (repeat(arange(n_mols), atoms_per_mol)); binary-search the segment.
__global__ __launch_bounds__(256)
void mol_mean_kernel(const float* __restrict__ ah, const int* __restrict__ mol_ids,
                     int n_atoms, float* __restrict__ out)
{
    const int m = blockIdx.x;
    __shared__ int s_start, s_end;
    if (threadIdx.x == 0) {
        int lo = 0, hi = n_atoms;
        while (lo < hi) { int mid = (lo + hi) >> 1; if (mol_ids[mid] <  m) lo = mid + 1; else hi = mid; }
        s_start = lo;
        lo = 0; hi = n_atoms;
        while (lo < hi) { int mid = (lo + hi) >> 1; if (mol_ids[mid] <= m) lo = mid + 1; else hi = mid; }
        s_end = lo;
    }
    __syncthreads();
    const int start = s_start;
    const int cnt   = s_end - s_start;
    const float inv = cnt > 0 ? 1.f / (float)cnt : 0.f;

    for (int h = threadIdx.x; h < HIDDEN; h += blockDim.x) {
        float s = 0.f;
        for (int a = 0; a < cnt; a++)
            s += ah[(size_t)(start + a) * HIDDEN + h];
        out[(size_t)m * HIDDEN + h] = s * inv;
    }
}

// ---------------- launch ----------------------------------------------------
extern "C" void kernel_launch(void* const* d_in, const int* in_sizes, int n_in,
                              void* d_out, int out_size)
{
    const float* fatoms = (const float*)d_in[0];
    const float* fbonds = (const float*)d_in[1];
    const int*   agraph = (const int*)d_in[2];
    const int*   bgraph = (const int*)d_in[3];
    const int*   mol_ids = (const int*)d_in[4];
    // d_in[5] = n_mols scalar on device (value recovered from out_size instead)
    const float* tree   = (const float*)d_in[6];
    const float* W_i    = (const float*)d_in[7];
    const float* W_h    = (const float*)d_in[8];
    const float* W_o    = (const float*)d_in[9];
    const float* b_o    = (const float*)d_in[10];
    float* out = (float*)d_out;

    const int n_atoms = in_sizes[0] / ATOM_FDIM;
    const int n_bonds = in_sizes[1] / (ATOM_FDIM + BOND_FDIM);
    const int n_mess  = in_sizes[6] / HIDDEN;
    const int n_mols  = out_size / HIDDEN;
    const int IN_FDIM = ATOM_FDIM + BOND_FDIM;   // 40
    const int OUT_K   = ATOM_FDIM + HIDDEN;      // 485

    float *binput, *gmsg, *nei;
    cudaGetSymbolAddress((void**)&binput, g_binput);
    cudaGetSymbolAddress((void**)&gmsg,   g_gmsg);
    cudaGetSymbolAddress((void**)&nei,    g_nei);

    dim3 blk(256);
    dim3 grid_b((HIDDEN + BN - 1) / BN, (n_bonds + BM - 1) / BM);
    dim3 grid_a((HIDDEN + BN - 1) / BN, (n_atoms + BM - 1) / BM);

    // init: binput = fbonds @ W_i^T ; gmsg = relu(binput)
    gemm_kernel<0><<<grid_b, blk>>>(fbonds, nullptr, 0, W_i, IN_FDIM,
                                    nullptr, nullptr, binput, gmsg,
                                    n_bonds, HIDDEN, IN_FDIM);

    // DEPTH-1 = 5 message-passing steps
    for (int it = 0; it < 5; it++) {
        gather_sum_kernel<<<n_bonds, blk>>>(bgraph, tree, n_mess, gmsg, nei);
        gemm_kernel<1><<<grid_b, blk>>>(nei, nullptr, 0, W_h, HIDDEN,
                                        binput, nullptr, gmsg, nullptr,
                                        n_bonds, HIDDEN, HIDDEN);
    }

    // atom aggregation + output layer (atom_hiddens reuses g_binput)
    gather_sum_kernel<<<n_atoms, blk>>>(agraph, tree, n_mess, gmsg, nei);
    gemm_kernel<2><<<grid_a, blk>>>(fatoms, nei, ATOM_FDIM, W_o, OUT_K,
                                    nullptr, b_o, binput, nullptr,
                                    n_atoms, HIDDEN, OUT_K);

    // per-molecule mean
    mol_mean_kernel<<<n_mols, blk>>>(binput, mol_ids, n_atoms, out);
}